// round 12
// baseline (speedup 1.0000x reference)
#include <cuda_runtime.h>
#include <cstdint>
#include <cstddef>

// Problem constants
#define SQ 2048      // sequence length
#define DK 2048      // d_model (GEMM K dim)
#define NB 2         // batch
#define NH 32        // q heads
#define NKV 8        // kv heads
#define HD 64        // head dim

// Scratch (device globals: no runtime allocation allowed)
__device__ float g_q [(size_t)NB * NH  * SQ * HD];   // [B,H,S,D]
__device__ float g_k [(size_t)NB * NKV * SQ * HD];   // [B,KV,S,D] (rope applied)
__device__ float g_v [(size_t)NB * NKV * SQ * HD];   // [B,KV,S,D]
__device__ float g_ao[(size_t)NB * SQ * NH * HD];    // [B,S,H*D]

// ---------------------------------------------------------------------------
// Packed f32x2 helpers (sm_103a: PTX-only FFMA2 path)
// ---------------------------------------------------------------------------
__device__ __forceinline__ unsigned long long bcast2(float x) {
  unsigned long long r;
  unsigned int u = __float_as_uint(x);
  asm("mov.b64 %0, {%1, %1};" : "=l"(r) : "r"(u));
  return r;
}
__device__ __forceinline__ unsigned long long pack2(float x, float y) {
  unsigned long long r;
  asm("mov.b64 %0, {%1, %2};" : "=l"(r)
      : "r"(__float_as_uint(x)), "r"(__float_as_uint(y)));
  return r;
}
__device__ __forceinline__ void fma2(unsigned long long& d,
                                     unsigned long long a,
                                     unsigned long long b) {
  asm("fma.rn.f32x2 %0, %1, %2, %0;" : "+l"(d) : "l"(a), "l"(b));
}
__device__ __forceinline__ void mul2(unsigned long long& d,
                                     unsigned long long a) {
  asm("mul.rn.f32x2 %0, %0, %1;" : "+l"(d) : "l"(a));
}
__device__ __forceinline__ float2 unpack2(unsigned long long v) {
  unsigned int lo, hi;
  asm("mov.b64 {%0, %1}, %2;" : "=r"(lo), "=r"(hi) : "l"(v));
  return make_float2(__uint_as_float(lo), __uint_as_float(hi));
}

// ---------------------------------------------------------------------------
// GEMM: C[M=4096, N=64-per-block] = A[4096, 2048] @ W[2048, N]
// BM=128, BN=64, BK=16, 128 threads, 8x8 micro-tile (f32x2 packed:
// 4 row-pairs x 8 cols = 32 FFMA2 per kk covering 64 FMAs; 4 LDS.128/kk
// -> 1.0 B smem per FMA, was 1.5 -- targets the measured L1=87% bottleneck).
// LDG.128 loaders + register prefetch + 2-stage smem double buffering.
// mode 0: plain row-major write to C (O projection), N = full row width
// mode 4: fused QKV — blockIdx.x in [0,32): Q (rope, ->Cq)
//                                  [32,40): K (rope, ->Ck)
//                                  [40,48): V (plain, ->Cv)
// ---------------------------------------------------------------------------
struct GemmSmem {
  union {
    struct { float As[2][16][132]; float Bs[2][16][68]; } ab;  // As is [k][m]
    float Cs[128][65];                                          // epilogue staging
  };
};

__global__ void __launch_bounds__(128)
gemm128x64(const float* __restrict__ A,
           const float* __restrict__ Wq, const float* __restrict__ Wk,
           const float* __restrict__ Wv,
           float* __restrict__ Cq, float* __restrict__ Ck,
           float* __restrict__ Cv,
           const float* __restrict__ rc, const float* __restrict__ rs, int mode)
{
  __shared__ GemmSmem sm;
  const int tid = threadIdx.x;
  const int tx = tid & 7;         // 8 col-groups of 8
  const int ty = tid >> 3;        // 16 row-groups of 8
  const int m0 = blockIdx.y * 128;

  // route block -> (weight, output, head-count, rope, N)
  int hx = blockIdx.x;
  bool rope = false;
  const float* W = Wq;
  float* Cout = Cq;
  int H = NH;
  int N = 64 * gridDim.x;          // mode 0: full row width
  if (mode == 4) {
    if (hx < 32)      { W = Wq; Cout = Cq; H = NH;  rope = true;  N = 2048; }
    else if (hx < 40) { hx -= 32; W = Wk; Cout = Ck; H = NKV; rope = true;  N = 512; }
    else              { hx -= 40; W = Wv; Cout = Cv; H = NKV; rope = false; N = 512; }
  }
  const int n0 = hx * 64;

  // acc2[ip][j]: packed pair of rows (ty*8+2*ip, ty*8+2*ip+1), col tx*8+j
  unsigned long long acc2[4][8];
#pragma unroll
  for (int i = 0; i < 4; i++)
#pragma unroll
    for (int j = 0; j < 8; j++) acc2[i][j] = 0ull;

  // Loaders (128 threads):
  // A: thread = row tid (0..127); 4 LDG.128 along k; 16 scalar STS (transpose)
  // B: thread (k = tid>>3, nq = tid&7); 2 LDG.128 / 2 STS.128 (nq, nq+8)
  const int bK  = tid >> 3;
  const int bNq = (tid & 7) * 4;

  const float* Aptr = A + (size_t)(m0 + tid) * DK;
  const float* Bptr = W + (size_t)bK * N + n0 + bNq;

  // prefetch tile 0 into registers, commit to stage 0
  float4 a0 = *(const float4*)(Aptr + 0);
  float4 a1 = *(const float4*)(Aptr + 4);
  float4 a2 = *(const float4*)(Aptr + 8);
  float4 a3 = *(const float4*)(Aptr + 12);
  float4 b0 = *(const float4*)(Bptr);
  float4 b1 = *(const float4*)(Bptr + 32);

  {
    const float av[16] = {a0.x,a0.y,a0.z,a0.w, a1.x,a1.y,a1.z,a1.w,
                          a2.x,a2.y,a2.z,a2.w, a3.x,a3.y,a3.z,a3.w};
#pragma unroll
    for (int u = 0; u < 16; u++) sm.ab.As[0][u][tid] = av[u];
    *(float4*)&sm.ab.Bs[0][bK][bNq] = b0;
    *(float4*)&sm.ab.Bs[0][bK][bNq + 32] = b1;
  }
  __syncthreads();

  for (int it = 0; it < DK / 16; it++) {
    const int st = it & 1;          // compute stage
    const bool more = (it + 1) < DK / 16;

    // issue next tile's LDGs early (retire during compute below)
    if (more) {
      const int k0n = (it + 1) * 16;
      a0 = *(const float4*)(Aptr + k0n + 0);
      a1 = *(const float4*)(Aptr + k0n + 4);
      a2 = *(const float4*)(Aptr + k0n + 8);
      a3 = *(const float4*)(Aptr + k0n + 12);
      b0 = *(const float4*)(Bptr + (size_t)k0n * N);
      b1 = *(const float4*)(Bptr + (size_t)k0n * N + 32);
    }

#pragma unroll
    for (int kk = 0; kk < 16; kk++) {
      // A side: 8 rows as 4 packed pairs (LDS.128 x2)
      ulonglong2 aA = *(const ulonglong2*)&sm.ab.As[st][kk][ty * 8];
      ulonglong2 aB = *(const ulonglong2*)&sm.ab.As[st][kk][ty * 8 + 4];
      const unsigned long long ap[4] = {aA.x, aA.y, aB.x, aB.y};
      // B side: 8 scalars (LDS.128 x2) broadcast to pairs
      float4 c0 = *(const float4*)&sm.ab.Bs[st][kk][tx * 8];
      float4 c1 = *(const float4*)&sm.ab.Bs[st][kk][tx * 8 + 4];
      const unsigned long long bb[8] = {
        bcast2(c0.x), bcast2(c0.y), bcast2(c0.z), bcast2(c0.w),
        bcast2(c1.x), bcast2(c1.y), bcast2(c1.z), bcast2(c1.w)};
#pragma unroll
      for (int ip = 0; ip < 4; ip++)
#pragma unroll
        for (int j = 0; j < 8; j++) fma2(acc2[ip][j], ap[ip], bb[j]);
    }

    // commit next tile to the other stage (prev readers fenced last iter)
    if (more) {
      const int sn = st ^ 1;
      const float av[16] = {a0.x,a0.y,a0.z,a0.w, a1.x,a1.y,a1.z,a1.w,
                            a2.x,a2.y,a2.z,a2.w, a3.x,a3.y,a3.z,a3.w};
#pragma unroll
      for (int u = 0; u < 16; u++) sm.ab.As[sn][u][tid] = av[u];
      *(float4*)&sm.ab.Bs[sn][bK][bNq] = b0;
      *(float4*)&sm.ab.Bs[sn][bK][bNq + 32] = b1;
    }
    __syncthreads();   // fences this stage's reads + next stage's writes
  }

  if (mode == 0) {
#pragma unroll
    for (int i = 0; i < 4; i++) {
      const int m = m0 + ty * 8 + 2 * i;
#pragma unroll
      for (int j = 0; j < 8; j++) {
        float2 u = unpack2(acc2[i][j]);
        Cout[(size_t)m * N + n0 + tx * 8 + j] = u.x;
        Cout[(size_t)(m + 1) * N + n0 + tx * 8 + j] = u.y;
      }
    }
  } else if (!rope) {
    // plain scatter to [B, H, S, 64]
#pragma unroll
    for (int i = 0; i < 4; i++) {
      const int m = m0 + ty * 8 + 2 * i;
      const int bb = m >> 11, s = m & (SQ - 1);
#pragma unroll
      for (int j = 0; j < 8; j++) {
        const int d = tx * 8 + j;
        float2 u = unpack2(acc2[i][j]);
        Cout[(((size_t)bb * H + hx) * SQ + s) * HD + d] = u.x;
        Cout[(((size_t)bb * H + hx) * SQ + s + 1) * HD + d] = u.y;
      }
    }
  } else {
    // RoPE: needs the pair element (d ^ 32) -> stage tile through smem.
#pragma unroll
    for (int i = 0; i < 4; i++)
#pragma unroll
      for (int j = 0; j < 8; j++) {
        float2 u = unpack2(acc2[i][j]);
        sm.Cs[ty * 8 + 2 * i][tx * 8 + j] = u.x;
        sm.Cs[ty * 8 + 2 * i + 1][tx * 8 + j] = u.y;
      }
    __syncthreads();
#pragma unroll
    for (int i = 0; i < 8; i++) {
      const int m = m0 + ty * 8 + i;
      const int bb = m >> 11, s = m & (SQ - 1);
#pragma unroll
      for (int j = 0; j < 8; j++) {
        const int d = tx * 8 + j;
        const int jj = d & 31;
        const float c = rc[s * 32 + jj];
        const float sn = rs[s * 32 + jj];
        float res;
        if (d < 32)
          res = sm.Cs[ty * 8 + i][d] * c - sm.Cs[ty * 8 + i][d + 32] * sn;
        else
          res = sm.Cs[ty * 8 + i][d - 32] * sn + sm.Cs[ty * 8 + i][d] * c;
        Cout[(((size_t)bb * H + hx) * SQ + s) * HD + d] = res;
      }
    }
  }
}

// ---------------------------------------------------------------------------
// Flash attention (fp32, causal, online softmax), f32x2 packed inner loops.
// One block = 64 query rows of one (b, h); 64 threads, 1 query row/thread.
// ---------------------------------------------------------------------------
#define ATTN_SMEM_FLOATS (64 * 68 + 64 * 68)
#define ATTN_SMEM_BYTES  (ATTN_SMEM_FLOATS * 4)

__global__ void __launch_bounds__(64)
attn_kernel(const float* __restrict__ q, const float* __restrict__ k,
            const float* __restrict__ v, float* __restrict__ ao)
{
  extern __shared__ float smf[];
  float* qs = smf;                     // 64*68
  float* kv = smf + 64 * 68;           // 64*68

  const int t  = threadIdx.x;
  const int qt = gridDim.x - 1 - blockIdx.x;  // heavy tiles launch first
  const int h  = blockIdx.y;
  const int b  = blockIdx.z;
  const int s0 = qt * 64;

  const float* qbase = q + (((size_t)b * NH + h) * SQ + s0) * HD;
  const size_t kvoff = ((size_t)b * NKV + (h >> 2)) * SQ * HD;
  const float* kbase = k + kvoff;
  const float* vbase = v + kvoff;

#pragma unroll 8
  for (int i = 0; i < 64; i++) qs[i * 68 + t] = qbase[i * HD + t];

  unsigned long long o2[32];
#pragma unroll
  for (int i = 0; i < 32; i++) o2[i] = 0ull;
  float mprev = -1e30f, l = 0.f;
  const int rg = s0 + t;

  for (int kt = 0; kt <= qt; kt++) {
    const int c0 = kt * 64;
    __syncthreads();
#pragma unroll 8
    for (int i = 0; i < 64; i++) kv[t * 68 + i] = kbase[(size_t)(c0 + i) * HD + t];
    __syncthreads();

    unsigned long long sc2[32];
#pragma unroll
    for (int i = 0; i < 32; i++) sc2[i] = 0ull;
#pragma unroll 2
    for (int d4 = 0; d4 < 16; d4++) {
      const float4 qv = *(const float4*)(qs + t * 68 + d4 * 4);
      const float qsc[4] = {qv.x, qv.y, qv.z, qv.w};
#pragma unroll
      for (int du = 0; du < 4; du++) {
        const int d = d4 * 4 + du;
        const unsigned long long qq = bcast2(qsc[du]);
#pragma unroll
        for (int cc = 0; cc < 16; cc++) {
          ulonglong2 kp = *(const ulonglong2*)(kv + d * 68 + cc * 4);
          fma2(sc2[cc * 2], kp.x, qq);
          fma2(sc2[cc * 2 + 1], kp.y, qq);
        }
      }
    }
    __syncthreads();

#pragma unroll 8
    for (int i = 0; i < 64; i++) kv[i * 68 + t] = vbase[(size_t)(c0 + i) * HD + t];

    float mnew = mprev;
    if (kt == qt) {
#pragma unroll
      for (int pi = 0; pi < 32; pi++) {
        float2 s = unpack2(sc2[pi]);
        float a0 = (c0 + 2 * pi     <= rg) ? s.x * 0.125f : -1e30f;
        float a1 = (c0 + 2 * pi + 1 <= rg) ? s.y * 0.125f : -1e30f;
        sc2[pi] = pack2(a0, a1);
        mnew = fmaxf(mnew, fmaxf(a0, a1));
      }
    } else {
#pragma unroll
      for (int pi = 0; pi < 32; pi++) {
        float2 s = unpack2(sc2[pi]);
        float a0 = s.x * 0.125f, a1 = s.y * 0.125f;
        sc2[pi] = pack2(a0, a1);
        mnew = fmaxf(mnew, fmaxf(a0, a1));
      }
    }
    const float corr = __expf(mprev - mnew);
    l *= corr;
    const unsigned long long cc2 = bcast2(corr);
#pragma unroll
    for (int i = 0; i < 32; i++) mul2(o2[i], cc2);

    float lsum = 0.f;
#pragma unroll
    for (int pi = 0; pi < 32; pi++) {
      float2 s = unpack2(sc2[pi]);
      const float p0 = __expf(s.x - mnew);
      const float p1 = __expf(s.y - mnew);
      lsum += p0 + p1;
      sc2[pi] = pack2(p0, p1);
    }
    l += lsum;
    mprev = mnew;
    __syncthreads();

#pragma unroll
    for (int pi = 0; pi < 32; pi++) {
      float2 pr = unpack2(sc2[pi]);
      const unsigned long long pp0 = bcast2(pr.x);
      const unsigned long long pp1 = bcast2(pr.y);
      const float* v0 = kv + (2 * pi) * 68;
      const float* v1 = kv + (2 * pi + 1) * 68;
#pragma unroll
      for (int dd = 0; dd < 16; dd++) {
        ulonglong2 vp = *(const ulonglong2*)(v0 + dd * 4);
        fma2(o2[dd * 2], vp.x, pp0);
        fma2(o2[dd * 2 + 1], vp.y, pp0);
      }
#pragma unroll
      for (int dd = 0; dd < 16; dd++) {
        ulonglong2 vp = *(const ulonglong2*)(v1 + dd * 4);
        fma2(o2[dd * 2], vp.x, pp1);
        fma2(o2[dd * 2 + 1], vp.y, pp1);
      }
    }
  }

  const float inv = 1.f / l;
  float* outp = ao + ((size_t)(b * SQ + s0 + t)) * (NH * HD) + h * HD;
#pragma unroll
  for (int pi = 0; pi < 32; pi++) {
    float2 u = unpack2(o2[pi]);
    *(float2*)(outp + 2 * pi) = make_float2(u.x * inv, u.y * inv);
  }
}

// ---------------------------------------------------------------------------
// Launch: fused QKV proj (1 launch) -> attention -> O proj
// ---------------------------------------------------------------------------
extern "C" void kernel_launch(void* const* d_in, const int* in_sizes, int n_in,
                              void* d_out, int out_size)
{
  const float* x  = (const float*)d_in[0];
  const float* Wq = (const float*)d_in[1];
  const float* Wk = (const float*)d_in[2];
  const float* Wv = (const float*)d_in[3];
  const float* Wo = (const float*)d_in[4];
  const float* rc = (const float*)d_in[5];
  const float* rs = (const float*)d_in[6];
  float* out = (float*)d_out;

  float *gq, *gk, *gv, *gao;
  cudaGetSymbolAddress((void**)&gq,  g_q);
  cudaGetSymbolAddress((void**)&gk,  g_k);
  cudaGetSymbolAddress((void**)&gv,  g_v);
  cudaGetSymbolAddress((void**)&gao, g_ao);

  cudaFuncSetAttribute(attn_kernel, cudaFuncAttributeMaxDynamicSharedMemorySize,
                       ATTN_SMEM_BYTES);

  // fused Q (rope) + K (rope) + V projections: 48 head-blocks x 32 m-tiles
  gemm128x64<<<dim3(48, 32), 128>>>(x, Wq, Wk, Wv, gq, gk, gv, rc, rs, 4);
  // attention: grid (q-tiles, heads, batch)
  attn_kernel<<<dim3(SQ / 64, NH, NB), 64, ATTN_SMEM_BYTES>>>(gq, gk, gv, gao);
  // output projection -> d_out (N = 64 * gridDim.x = 2048)
  gemm128x64<<<dim3(32, 32), 128>>>(gao, Wo, nullptr, nullptr, out, nullptr,
                                    nullptr, nullptr, nullptr, 0);
}